// round 16
// baseline (speedup 1.0000x reference)
#include <cuda_runtime.h>
#include <cstdint>

#define N_NODES 5000
#define BATCH   16
#define FEAT    512
#define NEDGE   160000
#define NCOL    64
#define FCOL    128
#define NTOT    (N_NODES*BATCH)   // 80000

// Scratch (device globals; zero-initialized at load; no allocation allowed)
__device__ __align__(16) float g_h1  [N_NODES*BATCH*16];
__device__ __align__(16) float g_buf1[N_NODES*BATCH*16];
__device__ __align__(16) float g_h2  [N_NODES*BATCH*16];
__device__ __align__(16) float g_buf2[N_NODES*BATCH*16];
__device__ __align__(16) float g_part[8*N_NODES*BATCH*16];  // split-K8 partials, [kh][r][16]
__device__ int   g_deg [N_NODES];          // zero at entry (re-zeroed in k_gather layer0)
__device__ int   g_cursor[N_NODES];        // ditto
__device__ int   g_rowstart[N_NODES+1];
__device__ float g_dinv[N_NODES];
__device__ __align__(16) int2 g_csr[NEDGE];   // x = src node, y = norm (float bits)
__device__ float g_col [BATCH*NCOL];

// ---- packed f32x2 helpers (Blackwell) ----
__device__ __forceinline__ unsigned long long splat2(float x){
    unsigned long long r; asm("mov.b64 %0, {%1, %1};" : "=l"(r) : "f"(x)); return r;
}
__device__ __forceinline__ unsigned long long ffma2(unsigned long long a, unsigned long long b, unsigned long long c){
    unsigned long long d; asm("fma.rn.f32x2 %0, %1, %2, %3;" : "=l"(d) : "l"(a), "l"(b), "l"(c)); return d;
}
__device__ __forceinline__ float2 unpack2(unsigned long long v){
    float2 r; asm("mov.b64 {%0, %1}, %2;" : "=f"(r.x), "=f"(r.y) : "l"(v)); return r;
}
__device__ __forceinline__ void fma4(float4& a, float nr, const float4& u){
    a.x = fmaf(nr, u.x, a.x); a.y = fmaf(nr, u.y, a.y);
    a.z = fmaf(nr, u.z, a.z); a.w = fmaf(nr, u.w, a.w);
}
__device__ __forceinline__ void cpasync16(uint32_t saddr, const void* gptr){
    asm volatile("cp.async.cg.shared.global [%0], [%1], 16;" :: "r"(saddr), "l"(gptr));
}

// edge_index is INT32 (proven). Layout [2, E]: src = ei[0..E), dst = ei[E..2E).

// ---- degree count: 4 edges per thread via int4 over the dst half ----
__global__ void k_count(const int* __restrict__ ei){
    int e4 = blockIdx.x*blockDim.x + threadIdx.x;
    if (e4 < NEDGE/4){
        int4 v = ((const int4*)(ei + NEDGE))[e4];
        atomicAdd(&g_deg[v.x], 1);
        atomicAdd(&g_deg[v.y], 1);
        atomicAdd(&g_deg[v.z], 1);
        atomicAdd(&g_deg[v.w], 1);
    }
}
// single-block exclusive scan over 5000 degree counts (+ dinv)
__global__ void __launch_bounds__(1024) k_scan(){
    __shared__ int part[1024];
    int t = threadIdx.x;
    const int CH = (N_NODES + 1023) / 1024;   // 5
    int base = t * CH;
    int s = 0;
    #pragma unroll
    for (int j = 0; j < CH; j++){ int idx = base + j; if (idx < N_NODES) s += g_deg[idx]; }
    part[t] = s; __syncthreads();
    for (int off = 1; off < 1024; off <<= 1){
        int v = (t >= off) ? part[t - off] : 0;
        __syncthreads();
        part[t] += v;
        __syncthreads();
    }
    int excl = (t == 0) ? 0 : part[t - 1];
    #pragma unroll
    for (int j = 0; j < CH; j++){
        int idx = base + j;
        if (idx < N_NODES){
            int d = g_deg[idx];
            g_rowstart[idx] = excl; excl += d;
            g_dinv[idx] = rsqrtf((float)(d + 1));
        }
    }
    if (t == 0) g_rowstart[N_NODES] = NEDGE;
}
// CSR fill: 2 edges per thread via int2 loads
__global__ void k_fill(const int* __restrict__ ei){
    int e2 = blockIdx.x*blockDim.x + threadIdx.x;
    if (e2 >= NEDGE/2) return;
    int2 sp = ((const int2*)ei)[e2];
    int2 dp = ((const int2*)(ei + NEDGE))[e2];
    {
        int pos = atomicAdd(&g_cursor[dp.x], 1);
        g_csr[g_rowstart[dp.x] + pos] = make_int2(sp.x, __float_as_int(g_dinv[sp.x]*g_dinv[dp.x]));
    }
    {
        int pos = atomicAdd(&g_cursor[dp.y], 1);
        g_csr[g_rowstart[dp.y] + pos] = make_int2(sp.y, __float_as_int(g_dinv[sp.y]*g_dinv[dp.y]));
    }
}

// ---- GEMM1 split-K8, cp.async, warp-autonomous staging, 2 ROWS PER THREAD ----
// grid (nblk, 8); block 64 (2 warps). Each warp owns 64 rows. rowblk0 = block-row offset.
#define GR 64
#define KC 16
#define KSPLIT 8
#define KQ (FEAT/KSPLIT)        // 64
#define CHUNKS (KQ/KC)          // 4
#define TSTRIDE 20
#define WTILE (64*TSTRIDE)      // floats per warp-buffer (5120 B)
__global__ void __launch_bounds__(GR, 8) k_gemm1(const float* __restrict__ X, const float* __restrict__ W1,
                                                 int rowblk0){
    __shared__ __align__(16) float ws[KQ*16];                 // 4 KB (this k-eighth of W)
    __shared__ __align__(16) float tile[2][2][WTILE];         // 2 warps x 2 bufs x 5 KB
    int t    = threadIdx.x;
    int w    = t >> 5;
    int lane = t & 31;
    int kh   = blockIdx.y;
    const float4* W14 = (const float4*)W1 + kh*(KQ*16/4);
    for (int i = t; i < KQ*16/4; i += GR)
        ((float4*)ws)[i] = W14[i];
    int wrow0 = (rowblk0 + blockIdx.x) * 128 + w*64;          // this warp's 64 rows
    const float4* Xw = (const float4*)X + (size_t)wrow0*(FEAT/4) + kh*(KQ/4);
    int rr[8], kq[8];
    #pragma unroll
    for (int i = 0; i < 8; i++){
        int f = lane + 32*i;
        rr[i] = f >> 2; kq[i] = f & 3;
    }
    uint32_t tb[2];
    tb[0] = (uint32_t)__cvta_generic_to_shared(&tile[w][0][0]);
    tb[1] = (uint32_t)__cvta_generic_to_shared(&tile[w][1][0]);
    #pragma unroll
    for (int i = 0; i < 8; i++)
        cpasync16(tb[0] + (rr[i]*TSTRIDE + kq[i]*4)*4, Xw + (size_t)rr[i]*(FEAT/4) + kq[i]);
    asm volatile("cp.async.commit_group;" ::: "memory");
    __syncthreads();   // ws visible to all warps
    unsigned long long acc0[8] = {0,0,0,0,0,0,0,0};
    unsigned long long acc1[8] = {0,0,0,0,0,0,0,0};
    for (int c = 0; c < CHUNKS; c++){
        if (c + 1 < CHUNKS){
            uint32_t dstb = tb[(c+1)&1];
            #pragma unroll
            for (int i = 0; i < 8; i++)
                cpasync16(dstb + (rr[i]*TSTRIDE + kq[i]*4)*4,
                          Xw + (size_t)rr[i]*(FEAT/4) + (c+1)*4 + kq[i]);
            asm volatile("cp.async.commit_group;" ::: "memory");
            asm volatile("cp.async.wait_group 1;" ::: "memory");
        } else {
            asm volatile("cp.async.wait_group 0;" ::: "memory");
        }
        __syncwarp();
        const float* tl = &tile[w][c&1][0];
        #pragma unroll
        for (int q = 0; q < 4; q++){
            float4 xv0 = *((const float4*)&tl[lane*TSTRIDE + q*4]);
            float4 xv1 = *((const float4*)&tl[(lane+32)*TSTRIDE + q*4]);
            int kbase = c*KC + q*4;
            #pragma unroll
            for (int kk = 0; kk < 4; kk++){
                float xs0 = (kk==0)?xv0.x:(kk==1)?xv0.y:(kk==2)?xv0.z:xv0.w;
                float xs1 = (kk==0)?xv1.x:(kk==1)?xv1.y:(kk==2)?xv1.z:xv1.w;
                unsigned long long a2 = splat2(xs0);
                unsigned long long b2 = splat2(xs1);
                const ulonglong2* wk = (const ulonglong2*)&ws[(kbase+kk)*16];
                ulonglong2 w0 = wk[0], w1 = wk[1], w2 = wk[2], w3 = wk[3];
                acc0[0]=ffma2(a2,w0.x,acc0[0]); acc0[1]=ffma2(a2,w0.y,acc0[1]);
                acc0[2]=ffma2(a2,w1.x,acc0[2]); acc0[3]=ffma2(a2,w1.y,acc0[3]);
                acc0[4]=ffma2(a2,w2.x,acc0[4]); acc0[5]=ffma2(a2,w2.y,acc0[5]);
                acc0[6]=ffma2(a2,w3.x,acc0[6]); acc0[7]=ffma2(a2,w3.y,acc0[7]);
                acc1[0]=ffma2(b2,w0.x,acc1[0]); acc1[1]=ffma2(b2,w0.y,acc1[1]);
                acc1[2]=ffma2(b2,w1.x,acc1[2]); acc1[3]=ffma2(b2,w1.y,acc1[3]);
                acc1[4]=ffma2(b2,w2.x,acc1[4]); acc1[5]=ffma2(b2,w2.y,acc1[5]);
                acc1[6]=ffma2(b2,w3.x,acc1[6]); acc1[7]=ffma2(b2,w3.y,acc1[7]);
            }
        }
        __syncwarp();
    }
    float4* dst0 = (float4*)g_part + ((size_t)kh*NTOT + wrow0 + lane)*4;
    float4* dst1 = (float4*)g_part + ((size_t)kh*NTOT + wrow0 + 32 + lane)*4;
    #pragma unroll
    for (int q = 0; q < 4; q++){
        float2 lo = unpack2(acc0[2*q]), hi = unpack2(acc0[2*q+1]);
        dst0[q] = make_float4(lo.x, lo.y, hi.x, hi.y);
    }
    #pragma unroll
    for (int q = 0; q < 4; q++){
        float2 lo = unpack2(acc1[2*q]), hi = unpack2(acc1[2*q+1]);
        dst1[q] = make_float4(lo.x, lo.y, hi.x, hi.y);
    }
}

// ---- reduce split-K8 partials + transpose to [n][b][16] layout (row range) ----
__global__ void k_red(int row0, int nrows){
    int i = blockIdx.x*256 + threadIdx.x;              // local float4 index
    if (i >= nrows*4) return;
    int r = row0 + (i >> 2);
    int q = i & 3;
    const float4* P = (const float4*)g_part;
    float4 s = P[(size_t)r*4 + q];
    #pragma unroll
    for (int j = 1; j < KSPLIT; j++){
        float4 p = P[(size_t)j*NTOT*4 + (size_t)r*4 + q];
        s.x += p.x; s.y += p.y; s.z += p.z; s.w += p.w;
    }
    int b = r / N_NODES, n = r - b*N_NODES;
    ((float4*)g_h1)[(n*16 + b)*4 + q] = s;
}

// ---- gather: buf[n][*] = dinv[n]^2 * h[n][*] + sum_{e: dst=n} norm_e * h[src_e][*] ----
// layer 0 also re-zeroes deg/cursor for the NEXT replay (runs strictly after k_fill).
__global__ void __launch_bounds__(256) k_gather(int layer){
    int gt = blockIdx.x*256 + threadIdx.x;
    if (layer == 0 && gt < N_NODES){ g_deg[gt] = 0; g_cursor[gt] = 0; }
    int n = gt >> 6;
    int i = gt & 63;
    if (n >= N_NODES) return;
    const float4* __restrict__ h  = (const float4*)(layer ? g_h2  : g_h1);
    float4*       __restrict__ bf = (float4*)      (layer ? g_buf2 : g_buf1);
    float di = g_dinv[n];
    float sl = di * di;
    float4 v = h[n*64 + i];
    float4 acc = make_float4(v.x*sl, v.y*sl, v.z*sl, v.w*sl);
    int k   = g_rowstart[n];
    int end = g_rowstart[n+1];
    for (; k + 8 <= end; k += 8){
        int2 e0 = g_csr[k+0], e1 = g_csr[k+1], e2 = g_csr[k+2], e3 = g_csr[k+3];
        int2 e4 = g_csr[k+4], e5 = g_csr[k+5], e6 = g_csr[k+6], e7 = g_csr[k+7];
        float4 u0 = h[e0.x*64 + i], u1 = h[e1.x*64 + i], u2 = h[e2.x*64 + i], u3 = h[e3.x*64 + i];
        float4 u4 = h[e4.x*64 + i], u5 = h[e5.x*64 + i], u6 = h[e6.x*64 + i], u7 = h[e7.x*64 + i];
        fma4(acc, __int_as_float(e0.y), u0); fma4(acc, __int_as_float(e1.y), u1);
        fma4(acc, __int_as_float(e2.y), u2); fma4(acc, __int_as_float(e3.y), u3);
        fma4(acc, __int_as_float(e4.y), u4); fma4(acc, __int_as_float(e5.y), u5);
        fma4(acc, __int_as_float(e6.y), u6); fma4(acc, __int_as_float(e7.y), u7);
    }
    for (; k + 4 <= end; k += 4){
        int2 e0 = g_csr[k+0], e1 = g_csr[k+1], e2 = g_csr[k+2], e3 = g_csr[k+3];
        float4 u0 = h[e0.x*64 + i], u1 = h[e1.x*64 + i], u2 = h[e2.x*64 + i], u3 = h[e3.x*64 + i];
        fma4(acc, __int_as_float(e0.y), u0); fma4(acc, __int_as_float(e1.y), u1);
        fma4(acc, __int_as_float(e2.y), u2); fma4(acc, __int_as_float(e3.y), u3);
    }
    for (; k < end; k++){
        int2 e = g_csr[k];
        float4 u = h[e.x*64 + i];
        fma4(acc, __int_as_float(e.y), u);
    }
    bf[n*64 + i] = acc;
}

// ---- layer2 input transform: h2 = relu(buf1 + b1) @ W2 (proven) ----
__global__ void __launch_bounds__(256) k_xform2(const float* __restrict__ W2, const float* __restrict__ b1){
    __shared__ float sw[256];
    __shared__ float sb[16];
    sw[threadIdx.x] = W2[threadIdx.x];
    if (threadIdx.x < 16) sb[threadIdx.x] = b1[threadIdx.x];
    __syncthreads();
    int r = blockIdx.x*256 + threadIdx.x;
    if (r >= NTOT) return;
    const float4* in = (const float4*)g_buf1 + (size_t)r*4;
    float v[16];
    #pragma unroll
    for (int q=0;q<4;q++){
        float4 t = in[q];
        v[4*q+0]=t.x; v[4*q+1]=t.y; v[4*q+2]=t.z; v[4*q+3]=t.w;
    }
    #pragma unroll
    for (int j=0;j<16;j++) v[j] = fmaxf(v[j] + sb[j], 0.0f);
    float o[16];
    #pragma unroll
    for (int j=0;j<16;j++) o[j] = 0.0f;
    #pragma unroll
    for (int j=0;j<16;j++){
        float vj = v[j];
        #pragma unroll
        for (int jo=0;jo<16;jo++) o[jo] = fmaf(vj, sw[j*16+jo], o[jo]);
    }
    float4* out = (float4*)g_h2 + (size_t)r*4;
    #pragma unroll
    for (int q=0;q<4;q++)
        out[q] = make_float4(o[4*q+0], o[4*q+1], o[4*q+2], o[4*q+3]);
}

// ---- column MLP: 32 threads per row (proven) ----
__global__ void __launch_bounds__(256) k_colmlp(const float* __restrict__ CF, const float* __restrict__ cw1,
                                                const float* __restrict__ cb1, const float* __restrict__ cw2,
                                                const float* __restrict__ cb2){
    __shared__ __align__(16) float sw[FCOL*16];    // [k][j]
    __shared__ float sb1[16], sw2[16], scb2;
    for (int i = threadIdx.x; i < FCOL*16/4; i += 256)
        ((float4*)sw)[i] = ((const float4*)cw1)[i];
    if (threadIdx.x < 16){ sb1[threadIdx.x]=cb1[threadIdx.x]; sw2[threadIdx.x]=cw2[threadIdx.x]; }
    if (threadIdx.x == 0) scb2 = cb2[0];
    __syncthreads();
    int gt = blockIdx.x*256 + threadIdx.x;
    int r    = gt >> 5;        // row 0..1023
    int lane = gt & 31;
    int j    = lane & 15;      // hidden unit
    int hf   = lane >> 4;      // k-half
    const float4* xr = (const float4*)CF + (size_t)r*(FCOL/4) + hf*(FCOL/8);
    float acc = hf ? 0.0f : sb1[j];
    #pragma unroll
    for (int k4 = 0; k4 < FCOL/8; k4++){
        float4 xv = xr[k4];
        int kb = (hf*(FCOL/8) + k4)*4;
        acc = fmaf(xv.x, sw[(kb+0)*16 + j], acc);
        acc = fmaf(xv.y, sw[(kb+1)*16 + j], acc);
        acc = fmaf(xv.z, sw[(kb+2)*16 + j], acc);
        acc = fmaf(xv.w, sw[(kb+3)*16 + j], acc);
    }
    acc += __shfl_xor_sync(0xffffffffu, acc, 16);   // merge k-halves (same j)
    float val = fmaxf(acc, 0.0f) * sw2[j];
    val += __shfl_xor_sync(0xffffffffu, val, 1);
    val += __shfl_xor_sync(0xffffffffu, val, 2);
    val += __shfl_xor_sync(0xffffffffu, val, 4);
    val += __shfl_xor_sync(0xffffffffu, val, 8);
    if (lane == 0) g_col[r] = val + scb2;
}

// ---- final: node head + broadcast add with col logits (proven) ----
__global__ void __launch_bounds__(256) k_final(const float* __restrict__ b2, const float* __restrict__ fcw,
                                               const float* __restrict__ fcb, float* __restrict__ out){
    __shared__ __align__(16) float scol[BATCH*NCOL];
    __shared__ float sb2[16], sfw[16];
    for (int i = threadIdx.x; i < BATCH*NCOL; i += 256) scol[i] = g_col[i];
    if (threadIdx.x < 16){ sb2[threadIdx.x]=b2[threadIdx.x]; sfw[threadIdx.x]=fcw[threadIdx.x]; }
    __syncthreads();
    int r = blockIdx.x*256 + threadIdx.x;
    if (r >= NTOT) return;
    int b = r / N_NODES, n = r - b*N_NODES;
    const float4* in = (const float4*)g_buf2 + ((size_t)n*16 + b)*4;
    float logit = fcb[0];
    #pragma unroll
    for (int q=0;q<4;q++){
        float4 t = in[q];
        logit = fmaf(fmaxf(t.x + sb2[4*q+0], 0.0f), sfw[4*q+0], logit);
        logit = fmaf(fmaxf(t.y + sb2[4*q+1], 0.0f), sfw[4*q+1], logit);
        logit = fmaf(fmaxf(t.z + sb2[4*q+2], 0.0f), sfw[4*q+2], logit);
        logit = fmaf(fmaxf(t.w + sb2[4*q+3], 0.0f), sfw[4*q+3], logit);
    }
    float4* o = (float4*)out + (size_t)r*16;          // out[b][n*64 + c]
    const float4* sc = (const float4*)scol + b*16;
    #pragma unroll
    for (int c4 = 0; c4 < 16; c4++){
        float4 cv = sc[c4];
        o[c4] = make_float4(logit+cv.x, logit+cv.y, logit+cv.z, logit+cv.w);
    }
}

#define RBLK_A 313                 // 313*128 = 40064 rows
#define RBLK_B 312                 // 312*128 = 39936 rows
#define ROWS_A (RBLK_A*128)
#define ROWS_B (RBLK_B*128)

extern "C" void kernel_launch(void* const* d_in, const int* in_sizes, int n_in,
                              void* d_out, int out_size){
    const float* X   = (const float*)d_in[0];
    const float* CF  = (const float*)d_in[1];
    const int*   ei  = (const int*)d_in[2];
    const float* W1  = (const float*)d_in[3];
    const float* b1  = (const float*)d_in[4];
    const float* W2  = (const float*)d_in[5];
    const float* b2  = (const float*)d_in[6];
    const float* fcw = (const float*)d_in[7];
    const float* fcb = (const float*)d_in[8];
    const float* cw1 = (const float*)d_in[9];
    const float* cb1 = (const float*)d_in[10];
    const float* cw2 = (const float*)d_in[11];
    const float* cb2 = (const float*)d_in[12];
    float* out = (float*)d_out;

    static cudaStream_t s_prep = nullptr;
    static cudaEvent_t evRoot = nullptr, evGa = nullptr, evSide = nullptr;
    if (s_prep == nullptr){
        cudaStreamCreateWithFlags(&s_prep, cudaStreamNonBlocking);
        cudaEventCreateWithFlags(&evRoot, cudaEventDisableTiming);
        cudaEventCreateWithFlags(&evGa,   cudaEventDisableTiming);
        cudaEventCreateWithFlags(&evSide, cudaEventDisableTiming);
    }

    // Fork side stream.
    cudaEventRecord(evRoot, 0);
    cudaStreamWaitEvent(s_prep, evRoot, 0);

    // Side stream: CSR prep.
    k_count <<<(NEDGE/4+255)/256, 256, 0, s_prep>>>(ei);
    k_scan  <<<1, 1024, 0, s_prep>>>();
    k_fill  <<<(NEDGE/2+255)/256, 256, 0, s_prep>>>(ei);

    // Main stream: gemm1 in two row-halves (gemm1_a is the 4th launch — profiled).
    k_gemm1 <<<dim3(RBLK_A, KSPLIT), GR>>>(X, W1, 0);
    cudaEventRecord(evGa, 0);
    k_gemm1 <<<dim3(RBLK_B, KSPLIT), GR>>>(X, W1, RBLK_A);

    // Side stream: reduce first half concurrent with gemm1_b; then colmlp.
    cudaStreamWaitEvent(s_prep, evGa, 0);
    k_red   <<<(ROWS_A*4+255)/256, 256, 0, s_prep>>>(0, ROWS_A);
    k_colmlp<<<(BATCH*NCOL*32)/256, 256, 0, s_prep>>>(CF, cw1, cb1, cw2, cb2);
    cudaEventRecord(evSide, s_prep);

    // Main stream: reduce second half, then join and run the serial tail.
    k_red   <<<(ROWS_B*4+255)/256, 256>>>(ROWS_A, ROWS_B);
    cudaStreamWaitEvent(0, evSide, 0);     // carries fill + red_a + colmlp deps
    k_gather<<<(N_NODES*64)/256 + 1, 256>>>(0);
    k_xform2<<<(NTOT+255)/256, 256>>>(W2, b1);
    k_gather<<<(N_NODES*64)/256 + 1, 256>>>(1);
    k_final <<<(NTOT+255)/256, 256>>>(b2, fcw, fcb, out);
}

// round 17
// speedup vs baseline: 1.1277x; 1.1277x over previous
#include <cuda_runtime.h>
#include <cstdint>

#define N_NODES 5000
#define BATCH   16
#define FEAT    512
#define NEDGE   160000
#define NCOL    64
#define FCOL    128
#define NTOT    (N_NODES*BATCH)   // 80000

// Scratch (device globals; zero-initialized at load; no allocation allowed)
__device__ __align__(16) float g_h1  [N_NODES*BATCH*16];
__device__ __align__(16) float g_buf1[N_NODES*BATCH*16];
__device__ __align__(16) float g_h2  [N_NODES*BATCH*16];
__device__ __align__(16) float g_buf2[N_NODES*BATCH*16];
__device__ __align__(16) float g_part[8*N_NODES*BATCH*16];  // split-K8 partials, [kh][r][16]
__device__ int   g_deg [N_NODES];          // zero at entry (re-zeroed in k_gather layer0)
__device__ int   g_cursor[N_NODES];        // ditto
__device__ int   g_rowstart[N_NODES+1];
__device__ float g_dinv[N_NODES];
__device__ __align__(16) int2 g_csr[NEDGE];   // x = src node, y = norm (float bits)
__device__ float g_col [BATCH*NCOL];

// ---- packed f32x2 helpers (Blackwell) ----
__device__ __forceinline__ unsigned long long splat2(float x){
    unsigned long long r; asm("mov.b64 %0, {%1, %1};" : "=l"(r) : "f"(x)); return r;
}
__device__ __forceinline__ unsigned long long ffma2(unsigned long long a, unsigned long long b, unsigned long long c){
    unsigned long long d; asm("fma.rn.f32x2 %0, %1, %2, %3;" : "=l"(d) : "l"(a), "l"(b), "l"(c)); return d;
}
__device__ __forceinline__ float2 unpack2(unsigned long long v){
    float2 r; asm("mov.b64 {%0, %1}, %2;" : "=f"(r.x), "=f"(r.y) : "l"(v)); return r;
}
__device__ __forceinline__ void fma4(float4& a, float nr, const float4& u){
    a.x = fmaf(nr, u.x, a.x); a.y = fmaf(nr, u.y, a.y);
    a.z = fmaf(nr, u.z, a.z); a.w = fmaf(nr, u.w, a.w);
}
__device__ __forceinline__ void cpasync16(uint32_t saddr, const void* gptr){
    asm volatile("cp.async.cg.shared.global [%0], [%1], 16;" :: "r"(saddr), "l"(gptr));
}

// edge_index is INT32 (proven). Layout [2, E]: src = ei[0..E), dst = ei[E..2E).

// ---- degree count: 4 edges per thread via int4 over the dst half ----
__global__ void k_count(const int* __restrict__ ei){
    int e4 = blockIdx.x*blockDim.x + threadIdx.x;
    if (e4 < NEDGE/4){
        int4 v = ((const int4*)(ei + NEDGE))[e4];
        atomicAdd(&g_deg[v.x], 1);
        atomicAdd(&g_deg[v.y], 1);
        atomicAdd(&g_deg[v.z], 1);
        atomicAdd(&g_deg[v.w], 1);
    }
}
// single-block exclusive scan over 5000 degree counts (+ dinv)
__global__ void __launch_bounds__(1024) k_scan(){
    __shared__ int part[1024];
    int t = threadIdx.x;
    const int CH = (N_NODES + 1023) / 1024;   // 5
    int base = t * CH;
    int s = 0;
    #pragma unroll
    for (int j = 0; j < CH; j++){ int idx = base + j; if (idx < N_NODES) s += g_deg[idx]; }
    part[t] = s; __syncthreads();
    for (int off = 1; off < 1024; off <<= 1){
        int v = (t >= off) ? part[t - off] : 0;
        __syncthreads();
        part[t] += v;
        __syncthreads();
    }
    int excl = (t == 0) ? 0 : part[t - 1];
    #pragma unroll
    for (int j = 0; j < CH; j++){
        int idx = base + j;
        if (idx < N_NODES){
            int d = g_deg[idx];
            g_rowstart[idx] = excl; excl += d;
            g_dinv[idx] = rsqrtf((float)(d + 1));
        }
    }
    if (t == 0) g_rowstart[N_NODES] = NEDGE;
}
// CSR fill: 2 edges per thread via int2 loads
__global__ void k_fill(const int* __restrict__ ei){
    int e2 = blockIdx.x*blockDim.x + threadIdx.x;
    if (e2 >= NEDGE/2) return;
    int2 sp = ((const int2*)ei)[e2];
    int2 dp = ((const int2*)(ei + NEDGE))[e2];
    {
        int pos = atomicAdd(&g_cursor[dp.x], 1);
        g_csr[g_rowstart[dp.x] + pos] = make_int2(sp.x, __float_as_int(g_dinv[sp.x]*g_dinv[dp.x]));
    }
    {
        int pos = atomicAdd(&g_cursor[dp.y], 1);
        g_csr[g_rowstart[dp.y] + pos] = make_int2(sp.y, __float_as_int(g_dinv[sp.y]*g_dinv[dp.y]));
    }
}

// ---- GEMM1 split-K8, cp.async, warp-autonomous staging, 2 ROWS PER THREAD ----
// grid (625, 8); block 64 (2 warps). Each warp owns 64 rows (lane and lane+32). (R15-proven)
#define GR 64
#define KC 16
#define KSPLIT 8
#define KQ (FEAT/KSPLIT)        // 64
#define CHUNKS (KQ/KC)          // 4
#define TSTRIDE 20
#define WTILE (64*TSTRIDE)      // floats per warp-buffer (5120 B)
__global__ void __launch_bounds__(GR, 8) k_gemm1(const float* __restrict__ X, const float* __restrict__ W1){
    __shared__ __align__(16) float ws[KQ*16];                 // 4 KB (this k-eighth of W)
    __shared__ __align__(16) float tile[2][2][WTILE];         // 2 warps x 2 bufs x 5 KB
    int t    = threadIdx.x;
    int w    = t >> 5;
    int lane = t & 31;
    int kh   = blockIdx.y;
    const float4* W14 = (const float4*)W1 + kh*(KQ*16/4);
    for (int i = t; i < KQ*16/4; i += GR)
        ((float4*)ws)[i] = W14[i];
    int wrow0 = blockIdx.x * 128 + w*64;                      // this warp's 64 rows
    const float4* Xw = (const float4*)X + (size_t)wrow0*(FEAT/4) + kh*(KQ/4);
    int rr[8], kq[8];
    #pragma unroll
    for (int i = 0; i < 8; i++){
        int f = lane + 32*i;
        rr[i] = f >> 2; kq[i] = f & 3;
    }
    uint32_t tb[2];
    tb[0] = (uint32_t)__cvta_generic_to_shared(&tile[w][0][0]);
    tb[1] = (uint32_t)__cvta_generic_to_shared(&tile[w][1][0]);
    #pragma unroll
    for (int i = 0; i < 8; i++)
        cpasync16(tb[0] + (rr[i]*TSTRIDE + kq[i]*4)*4, Xw + (size_t)rr[i]*(FEAT/4) + kq[i]);
    asm volatile("cp.async.commit_group;" ::: "memory");
    __syncthreads();   // ws visible to all warps
    unsigned long long acc0[8] = {0,0,0,0,0,0,0,0};
    unsigned long long acc1[8] = {0,0,0,0,0,0,0,0};
    for (int c = 0; c < CHUNKS; c++){
        if (c + 1 < CHUNKS){
            uint32_t dstb = tb[(c+1)&1];
            #pragma unroll
            for (int i = 0; i < 8; i++)
                cpasync16(dstb + (rr[i]*TSTRIDE + kq[i]*4)*4,
                          Xw + (size_t)rr[i]*(FEAT/4) + (c+1)*4 + kq[i]);
            asm volatile("cp.async.commit_group;" ::: "memory");
            asm volatile("cp.async.wait_group 1;" ::: "memory");
        } else {
            asm volatile("cp.async.wait_group 0;" ::: "memory");
        }
        __syncwarp();
        const float* tl = &tile[w][c&1][0];
        #pragma unroll
        for (int q = 0; q < 4; q++){
            float4 xv0 = *((const float4*)&tl[lane*TSTRIDE + q*4]);
            float4 xv1 = *((const float4*)&tl[(lane+32)*TSTRIDE + q*4]);
            int kbase = c*KC + q*4;
            #pragma unroll
            for (int kk = 0; kk < 4; kk++){
                float xs0 = (kk==0)?xv0.x:(kk==1)?xv0.y:(kk==2)?xv0.z:xv0.w;
                float xs1 = (kk==0)?xv1.x:(kk==1)?xv1.y:(kk==2)?xv1.z:xv1.w;
                unsigned long long a2 = splat2(xs0);
                unsigned long long b2 = splat2(xs1);
                const ulonglong2* wk = (const ulonglong2*)&ws[(kbase+kk)*16];
                ulonglong2 w0 = wk[0], w1 = wk[1], w2 = wk[2], w3 = wk[3];
                acc0[0]=ffma2(a2,w0.x,acc0[0]); acc0[1]=ffma2(a2,w0.y,acc0[1]);
                acc0[2]=ffma2(a2,w1.x,acc0[2]); acc0[3]=ffma2(a2,w1.y,acc0[3]);
                acc0[4]=ffma2(a2,w2.x,acc0[4]); acc0[5]=ffma2(a2,w2.y,acc0[5]);
                acc0[6]=ffma2(a2,w3.x,acc0[6]); acc0[7]=ffma2(a2,w3.y,acc0[7]);
                acc1[0]=ffma2(b2,w0.x,acc1[0]); acc1[1]=ffma2(b2,w0.y,acc1[1]);
                acc1[2]=ffma2(b2,w1.x,acc1[2]); acc1[3]=ffma2(b2,w1.y,acc1[3]);
                acc1[4]=ffma2(b2,w2.x,acc1[4]); acc1[5]=ffma2(b2,w2.y,acc1[5]);
                acc1[6]=ffma2(b2,w3.x,acc1[6]); acc1[7]=ffma2(b2,w3.y,acc1[7]);
            }
        }
        __syncwarp();
    }
    float4* dst0 = (float4*)g_part + ((size_t)kh*NTOT + wrow0 + lane)*4;
    float4* dst1 = (float4*)g_part + ((size_t)kh*NTOT + wrow0 + 32 + lane)*4;
    #pragma unroll
    for (int q = 0; q < 4; q++){
        float2 lo = unpack2(acc0[2*q]), hi = unpack2(acc0[2*q+1]);
        dst0[q] = make_float4(lo.x, lo.y, hi.x, hi.y);
    }
    #pragma unroll
    for (int q = 0; q < 4; q++){
        float2 lo = unpack2(acc1[2*q]), hi = unpack2(acc1[2*q+1]);
        dst1[q] = make_float4(lo.x, lo.y, hi.x, hi.y);
    }
}

// ---- reduce split-K8 partials + transpose to [n][b][16] layout ----
__global__ void k_red(){
    int i = blockIdx.x*256 + threadIdx.x;              // < NTOT*4 float4s
    if (i >= NTOT*4) return;
    const float4* P = (const float4*)g_part;
    float4 s = P[i];
    #pragma unroll
    for (int j = 1; j < KSPLIT; j++){
        float4 p = P[(size_t)j*NTOT*4 + i];
        s.x += p.x; s.y += p.y; s.z += p.z; s.w += p.w;
    }
    int r = i >> 2, q = i & 3;
    int b = r / N_NODES, n = r - b*N_NODES;
    ((float4*)g_h1)[(n*16 + b)*4 + q] = s;
}

// ---- gather, 2-way edge split: 128 threads per node ----
// gt = n*128 + half*64 + i. Each half accumulates over half the edge list;
// partials combined via smem. Layer 0 also re-zeroes deg/cursor (after k_fill).
__global__ void __launch_bounds__(256) k_gather(int layer){
    __shared__ __align__(16) float4 sp[256];
    int gt = blockIdx.x*256 + threadIdx.x;             // grid exact: N_NODES*128
    if (layer == 0 && gt < N_NODES){ g_deg[gt] = 0; g_cursor[gt] = 0; }
    int n    = gt >> 7;
    int half = (gt >> 6) & 1;
    int i    = gt & 63;
    const float4* __restrict__ h  = (const float4*)(layer ? g_h2  : g_h1);
    float4*       __restrict__ bf = (float4*)      (layer ? g_buf2 : g_buf1);
    int start = g_rowstart[n];
    int end   = g_rowstart[n+1];
    int mid   = start + ((end - start) >> 1);
    int k     = half ? mid : start;
    int kend  = half ? end : mid;
    float4 acc;
    if (half == 0){
        float di = g_dinv[n];
        float sl = di * di;
        float4 v = h[n*64 + i];
        acc = make_float4(v.x*sl, v.y*sl, v.z*sl, v.w*sl);
    } else {
        acc = make_float4(0.f, 0.f, 0.f, 0.f);
    }
    for (; k + 8 <= kend; k += 8){
        int2 e0 = g_csr[k+0], e1 = g_csr[k+1], e2 = g_csr[k+2], e3 = g_csr[k+3];
        int2 e4 = g_csr[k+4], e5 = g_csr[k+5], e6 = g_csr[k+6], e7 = g_csr[k+7];
        float4 u0 = h[e0.x*64 + i], u1 = h[e1.x*64 + i], u2 = h[e2.x*64 + i], u3 = h[e3.x*64 + i];
        float4 u4 = h[e4.x*64 + i], u5 = h[e5.x*64 + i], u6 = h[e6.x*64 + i], u7 = h[e7.x*64 + i];
        fma4(acc, __int_as_float(e0.y), u0); fma4(acc, __int_as_float(e1.y), u1);
        fma4(acc, __int_as_float(e2.y), u2); fma4(acc, __int_as_float(e3.y), u3);
        fma4(acc, __int_as_float(e4.y), u4); fma4(acc, __int_as_float(e5.y), u5);
        fma4(acc, __int_as_float(e6.y), u6); fma4(acc, __int_as_float(e7.y), u7);
    }
    for (; k + 4 <= kend; k += 4){
        int2 e0 = g_csr[k+0], e1 = g_csr[k+1], e2 = g_csr[k+2], e3 = g_csr[k+3];
        float4 u0 = h[e0.x*64 + i], u1 = h[e1.x*64 + i], u2 = h[e2.x*64 + i], u3 = h[e3.x*64 + i];
        fma4(acc, __int_as_float(e0.y), u0); fma4(acc, __int_as_float(e1.y), u1);
        fma4(acc, __int_as_float(e2.y), u2); fma4(acc, __int_as_float(e3.y), u3);
    }
    for (; k < kend; k++){
        int2 e = g_csr[k];
        float4 u = h[e.x*64 + i];
        fma4(acc, __int_as_float(e.y), u);
    }
    sp[threadIdx.x] = acc;
    __syncthreads();
    if (half == 0){
        float4 p = sp[threadIdx.x + 64];
        acc.x += p.x; acc.y += p.y; acc.z += p.z; acc.w += p.w;
        bf[n*64 + i] = acc;
    }
}

// ---- layer2 input transform: h2 = relu(buf1 + b1) @ W2 (proven) ----
__global__ void __launch_bounds__(256) k_xform2(const float* __restrict__ W2, const float* __restrict__ b1){
    __shared__ float sw[256];
    __shared__ float sb[16];
    sw[threadIdx.x] = W2[threadIdx.x];
    if (threadIdx.x < 16) sb[threadIdx.x] = b1[threadIdx.x];
    __syncthreads();
    int r = blockIdx.x*256 + threadIdx.x;
    if (r >= NTOT) return;
    const float4* in = (const float4*)g_buf1 + (size_t)r*4;
    float v[16];
    #pragma unroll
    for (int q=0;q<4;q++){
        float4 t = in[q];
        v[4*q+0]=t.x; v[4*q+1]=t.y; v[4*q+2]=t.z; v[4*q+3]=t.w;
    }
    #pragma unroll
    for (int j=0;j<16;j++) v[j] = fmaxf(v[j] + sb[j], 0.0f);
    float o[16];
    #pragma unroll
    for (int j=0;j<16;j++) o[j] = 0.0f;
    #pragma unroll
    for (int j=0;j<16;j++){
        float vj = v[j];
        #pragma unroll
        for (int jo=0;jo<16;jo++) o[jo] = fmaf(vj, sw[j*16+jo], o[jo]);
    }
    float4* out = (float4*)g_h2 + (size_t)r*4;
    #pragma unroll
    for (int q=0;q<4;q++)
        out[q] = make_float4(o[4*q+0], o[4*q+1], o[4*q+2], o[4*q+3]);
}

// ---- column MLP: 32 threads per row (proven) ----
__global__ void __launch_bounds__(256) k_colmlp(const float* __restrict__ CF, const float* __restrict__ cw1,
                                                const float* __restrict__ cb1, const float* __restrict__ cw2,
                                                const float* __restrict__ cb2){
    __shared__ __align__(16) float sw[FCOL*16];    // [k][j]
    __shared__ float sb1[16], sw2[16], scb2;
    for (int i = threadIdx.x; i < FCOL*16/4; i += 256)
        ((float4*)sw)[i] = ((const float4*)cw1)[i];
    if (threadIdx.x < 16){ sb1[threadIdx.x]=cb1[threadIdx.x]; sw2[threadIdx.x]=cw2[threadIdx.x]; }
    if (threadIdx.x == 0) scb2 = cb2[0];
    __syncthreads();
    int gt = blockIdx.x*256 + threadIdx.x;
    int r    = gt >> 5;        // row 0..1023
    int lane = gt & 31;
    int j    = lane & 15;      // hidden unit
    int hf   = lane >> 4;      // k-half
    const float4* xr = (const float4*)CF + (size_t)r*(FCOL/4) + hf*(FCOL/8);
    float acc = hf ? 0.0f : sb1[j];
    #pragma unroll
    for (int k4 = 0; k4 < FCOL/8; k4++){
        float4 xv = xr[k4];
        int kb = (hf*(FCOL/8) + k4)*4;
        acc = fmaf(xv.x, sw[(kb+0)*16 + j], acc);
        acc = fmaf(xv.y, sw[(kb+1)*16 + j], acc);
        acc = fmaf(xv.z, sw[(kb+2)*16 + j], acc);
        acc = fmaf(xv.w, sw[(kb+3)*16 + j], acc);
    }
    acc += __shfl_xor_sync(0xffffffffu, acc, 16);   // merge k-halves (same j)
    float val = fmaxf(acc, 0.0f) * sw2[j];
    val += __shfl_xor_sync(0xffffffffu, val, 1);
    val += __shfl_xor_sync(0xffffffffu, val, 2);
    val += __shfl_xor_sync(0xffffffffu, val, 4);
    val += __shfl_xor_sync(0xffffffffu, val, 8);
    if (lane == 0) g_col[r] = val + scb2;
}

// ---- final: node head + broadcast add with col logits (proven) ----
__global__ void __launch_bounds__(256) k_final(const float* __restrict__ b2, const float* __restrict__ fcw,
                                               const float* __restrict__ fcb, float* __restrict__ out){
    __shared__ __align__(16) float scol[BATCH*NCOL];
    __shared__ float sb2[16], sfw[16];
    for (int i = threadIdx.x; i < BATCH*NCOL; i += 256) scol[i] = g_col[i];
    if (threadIdx.x < 16){ sb2[threadIdx.x]=b2[threadIdx.x]; sfw[threadIdx.x]=fcw[threadIdx.x]; }
    __syncthreads();
    int r = blockIdx.x*256 + threadIdx.x;
    if (r >= NTOT) return;
    int b = r / N_NODES, n = r - b*N_NODES;
    const float4* in = (const float4*)g_buf2 + ((size_t)n*16 + b)*4;
    float logit = fcb[0];
    #pragma unroll
    for (int q=0;q<4;q++){
        float4 t = in[q];
        logit = fmaf(fmaxf(t.x + sb2[4*q+0], 0.0f), sfw[4*q+0], logit);
        logit = fmaf(fmaxf(t.y + sb2[4*q+1], 0.0f), sfw[4*q+1], logit);
        logit = fmaf(fmaxf(t.z + sb2[4*q+2], 0.0f), sfw[4*q+2], logit);
        logit = fmaf(fmaxf(t.w + sb2[4*q+3], 0.0f), sfw[4*q+3], logit);
    }
    float4* o = (float4*)out + (size_t)r*16;          // out[b][n*64 + c]
    const float4* sc = (const float4*)scol + b*16;
    #pragma unroll
    for (int c4 = 0; c4 < 16; c4++){
        float4 cv = sc[c4];
        o[c4] = make_float4(logit+cv.x, logit+cv.y, logit+cv.z, logit+cv.w);
    }
}

extern "C" void kernel_launch(void* const* d_in, const int* in_sizes, int n_in,
                              void* d_out, int out_size){
    const float* X   = (const float*)d_in[0];
    const float* CF  = (const float*)d_in[1];
    const int*   ei  = (const int*)d_in[2];
    const float* W1  = (const float*)d_in[3];
    const float* b1  = (const float*)d_in[4];
    const float* W2  = (const float*)d_in[5];
    const float* b2  = (const float*)d_in[6];
    const float* fcw = (const float*)d_in[7];
    const float* fcb = (const float*)d_in[8];
    const float* cw1 = (const float*)d_in[9];
    const float* cb1 = (const float*)d_in[10];
    const float* cw2 = (const float*)d_in[11];
    const float* cb2 = (const float*)d_in[12];
    float* out = (float*)d_out;

    static cudaStream_t s_prep = nullptr;
    static cudaEvent_t evRoot = nullptr, evFill = nullptr, evCol = nullptr;
    if (s_prep == nullptr){
        cudaStreamCreateWithFlags(&s_prep, cudaStreamNonBlocking);
        cudaEventCreateWithFlags(&evRoot, cudaEventDisableTiming);
        cudaEventCreateWithFlags(&evFill, cudaEventDisableTiming);
        cudaEventCreateWithFlags(&evCol,  cudaEventDisableTiming);
    }

    // Fork: prep chain + colmlp run concurrent with gemm1 + k_red. (R15-proven)
    cudaEventRecord(evRoot, 0);
    cudaStreamWaitEvent(s_prep, evRoot, 0);

    k_count <<<(NEDGE/4+255)/256, 256, 0, s_prep>>>(ei);
    k_scan  <<<1, 1024, 0, s_prep>>>();
    k_fill  <<<(NEDGE/2+255)/256, 256, 0, s_prep>>>(ei);
    cudaEventRecord(evFill, s_prep);
    k_colmlp<<<(BATCH*NCOL*32)/256, 256, 0, s_prep>>>(CF, cw1, cb1, cw2, cb2);
    cudaEventRecord(evCol, s_prep);

    k_gemm1 <<<dim3(625, KSPLIT), GR>>>(X, W1);
    k_red   <<<(NTOT*4+255)/256, 256>>>();

    cudaStreamWaitEvent(0, evFill, 0);     // gather needs CSR
    k_gather<<<(N_NODES*128)/256, 256>>>(0);
    k_xform2<<<(NTOT+255)/256, 256>>>(W2, b1);
    k_gather<<<(N_NODES*128)/256, 256>>>(1);
    cudaStreamWaitEvent(0, evCol, 0);      // final needs col logits
    k_final <<<(NTOT+255)/256, 256>>>(b2, fcw, fcb, out);
}